// round 8
// baseline (speedup 1.0000x reference)
#include <cuda_runtime.h>
#include <math.h>
#include <cstdint>

#define S_TOK 4096
#define NH    12
#define HD    64
#define NROWS (S_TOK*NH)
#define QTILE 128
#define KTILE 32
#define NTILES (S_TOK/KTILE)

// SMEM geometry (floats)
#define KSTR 68
#define VSTR 72
#define QSTR 76
#define K_OFF   0
#define K_BUF_B (32*KSTR*4)
#define V_OFF   (2*K_BUF_B)
#define V_BUF_B (32*VSTR*4)
#define QP_OFF  (V_OFF + 2*V_BUF_B)
#define SMEM_BYTES (QP_OFF + 128*QSTR*4)   // 74752 -> 3 CTAs/SM

// ---------------- scratch ---------------------------------------------------
__device__ float g_k[(size_t)NH*S_TOK*HD];   // [h][s][d'], dims permuted in 8-groups
__device__ float g_v[(size_t)NH*S_TOK*HD];   // [h][s][d],  natural
__device__ float g_P[4][16];
__device__ float g_PT[4][16];
__device__ float g_Pinv[4][16];
__device__ float g_cos[32][8];
__device__ float g_sin[32][8];

__device__ __forceinline__ float tf32r(float x) {
    float r; asm("cvt.rna.tf32.f32 %0,%1;" : "=f"(r) : "f"(x)); return r;
}
__device__ __forceinline__ float ex2(float x) {
    float y; asm("ex2.approx.ftz.f32 %0,%1;" : "=f"(y) : "f"(x)); return y;
}
__device__ __forceinline__ uint32_t smem_u32(const void* p) {
    uint32_t a;
    asm("{ .reg .u64 t; cvta.to.shared.u64 t, %1; cvt.u32.u64 %0, t; }" : "=r"(a) : "l"(p));
    return a;
}
__device__ __forceinline__ void cp16(uint32_t dst, const void* src) {
    asm volatile("cp.async.cg.shared.global [%0], [%1], 16;" :: "r"(dst), "l"(src) : "memory");
}
#define CP_COMMIT() asm volatile("cp.async.commit_group;" ::: "memory")
#define CP_WAIT0()  asm volatile("cp.async.wait_group 0;" ::: "memory")

__device__ __forceinline__ void mma_tf32(float* d, const uint32_t* a, float b0f, float b1f) {
    uint32_t b0 = __float_as_uint(b0f), b1 = __float_as_uint(b1f);
    asm volatile("mma.sync.aligned.m16n8k8.row.col.f32.tf32.tf32.f32 "
        "{%0,%1,%2,%3}, {%4,%5,%6,%7}, {%8,%9}, {%0,%1,%2,%3};"
        : "+f"(d[0]), "+f"(d[1]), "+f"(d[2]), "+f"(d[3])
        : "r"(a[0]), "r"(a[1]), "r"(a[2]), "r"(a[3]), "r"(b0), "r"(b1));
}

__device__ __forceinline__ void mm4(const float* A, const float* B, float* Cm) {
#pragma unroll
    for (int i = 0; i < 4; i++)
#pragma unroll
        for (int j = 0; j < 4; j++) {
            float s = 0.f;
#pragma unroll
            for (int kk = 0; kk < 4; kk++) s += A[i*4+kk] * B[kk*4+j];
            Cm[i*4+j] = s;
        }
}

// key permutation within 8-group (GEMM1 D-layout == GEMM2 A-layout)
__device__ __forceinline__ int kperm(int row) {
    int b = row & 7;
    int pb = (b < 4) ? (b << 1) : (((b - 4) << 1) | 1);
    return (row & ~7) | pb;
}

// ---------------------------------------------------------------------------
__global__ void prep_kernel(const float* __restrict__ vm, const float* __restrict__ Ks) {
    int t = threadIdx.x;
    if (t < 32) {
        float L = log2f(100.0f);
#pragma unroll
        for (int i = 0; i < 8; i++) {
            float f = exp2f(-L * (float)i / 8.0f);
            float sv, cv; sincosf((float)t * f, &sv, &cv);
            g_cos[t][i] = cv; g_sin[t][i] = sv;
        }
    }
    if (t < 4) {
        int c = t;
        const float* V  = vm + c*16;
        const float* Kc = Ks + c*9;
        float a = Kc[0] * (1.0f/512.0f);
        float b = Kc[4] * (1.0f/512.0f);
        float u = Kc[2] * (1.0f/512.0f) - 0.5f;
        float w = Kc[5] * (1.0f/512.0f) - 0.5f;
        float K4[16] = {a,0,u,0, 0,b,w,0, 0,0,1,0, 0,0,0,1};
        float Vl[16];
#pragma unroll
        for (int i = 0; i < 16; i++) Vl[i] = V[i];
        float P[16];
        mm4(K4, Vl, P);
#pragma unroll
        for (int i = 0; i < 4; i++)
#pragma unroll
            for (int jj = 0; jj < 4; jj++) { g_P[c][i*4+jj] = P[i*4+jj]; g_PT[c][i*4+jj] = P[jj*4+i]; }
        float Sm[16];
#pragma unroll
        for (int i = 0; i < 3; i++)
#pragma unroll
            for (int jj = 0; jj < 3; jj++) Sm[i*4+jj] = Vl[jj*4+i];
#pragma unroll
        for (int i = 0; i < 3; i++)
            Sm[i*4+3] = -(Sm[i*4+0]*Vl[3] + Sm[i*4+1]*Vl[7] + Sm[i*4+2]*Vl[11]);
        Sm[12]=0.f; Sm[13]=0.f; Sm[14]=0.f; Sm[15]=1.f;
        float Ki[16] = {1.0f/a,0,-u/a,0, 0,1.0f/b,-w/b,0, 0,0,1,0, 0,0,0,1};
        float Pi[16];
        mm4(Sm, Ki, Pi);
#pragma unroll
        for (int i = 0; i < 16; i++) g_Pinv[c][i] = Pi[i];
    }
}

// ---------------------------------------------------------------------------
__device__ __forceinline__ void transform_row_y(
    const float* __restrict__ in, float* __restrict__ y,
    const float* M, int px, int py)
{
    float x[64];
    const float4* in4 = (const float4*)in;
#pragma unroll
    for (int i = 0; i < 16; i++) {
        float4 tv = in4[i];
        x[4*i+0]=tv.x; x[4*i+1]=tv.y; x[4*i+2]=tv.z; x[4*i+3]=tv.w;
    }
#pragma unroll
    for (int g = 0; g < 8; g++)
#pragma unroll
        for (int i = 0; i < 4; i++)
            y[g*4+i] = M[i*4+0]*x[g*4+0] + M[i*4+1]*x[g*4+1]
                     + M[i*4+2]*x[g*4+2] + M[i*4+3]*x[g*4+3];
#pragma unroll
    for (int i = 0; i < 8; i++) {
        float c1 = g_cos[px][i], s1 = g_sin[px][i];
        y[32+i] =  c1*x[32+i] + s1*x[40+i];
        y[40+i] = -s1*x[32+i] + c1*x[40+i];
        float c2 = g_cos[py][i], s2 = g_sin[py][i];
        y[48+i] =  c2*x[48+i] + s2*x[56+i];
        y[56+i] = -s2*x[48+i] + c2*x[56+i];
    }
}

__global__ void transform_kv_kernel(const float* __restrict__ k, const float* __restrict__ v) {
    int r = blockIdx.x * blockDim.x + threadIdx.x;
    if (r >= NROWS) return;
    int s = r / NH;
    int h = r - s * NH;
    int c  = s >> 10;
    int px = s & 31;
    int py = (s >> 5) & 31;
    float M[16];
#pragma unroll
    for (int i = 0; i < 16; i++) M[i] = g_Pinv[c][i];
    size_t ibase = (size_t)r * HD;
    size_t obase = ((size_t)h * S_TOK + s) * HD;

    float y[64];
    // K: dim-permuted within 8-groups (register shuffle before coalesced stores)
    transform_row_y(k + ibase, y, M, px, py);
    {
        float4* o4 = (float4*)(g_k + obase);
#pragma unroll
        for (int i = 0; i < 16; i++) {
            int b = (i >> 1) * 8;
            if ((i & 1) == 0)
                o4[i] = make_float4(tf32r(y[b+0]), tf32r(y[b+4]), tf32r(y[b+1]), tf32r(y[b+5]));
            else
                o4[i] = make_float4(tf32r(y[b+2]), tf32r(y[b+6]), tf32r(y[b+3]), tf32r(y[b+7]));
        }
    }
    // V: natural order
    transform_row_y(v + ibase, y, M, px, py);
    {
        float4* o4 = (float4*)(g_v + obase);
#pragma unroll
        for (int i = 0; i < 16; i++)
            o4[i] = make_float4(tf32r(y[4*i+0]), tf32r(y[4*i+1]), tf32r(y[4*i+2]), tf32r(y[4*i+3]));
    }
}

// ---------------------------------------------------------------------------
// Flash attention: mma.sync tf32, cp.async double buffer, key-permuted K
// (no P round-trip), dim-permuted Q/K (LDS.64 fragments), Q reloaded from
// SMEM each tile to fit 3 CTAs/SM.
// ---------------------------------------------------------------------------
__global__ void __launch_bounds__(QTILE, 3)
attn_kernel(const float* __restrict__ q, float* __restrict__ out) {
    extern __shared__ char smraw[];
    const uint32_t sb = smem_u32(smraw);
    float* smf = (float*)smraw;
    float* QP  = (float*)(smraw + QP_OFF);

    const int tid  = threadIdx.x;
    const int w    = tid >> 5, lane = tid & 31;
    const int g    = lane >> 2, j = lane & 3;
    const int h    = blockIdx.y;
    const int s    = blockIdx.x * QTILE + tid;
    const int cam  = s >> 10, px = s & 31, py = (s >> 5) & 31;

    const float* kg = g_k + (size_t)h * S_TOK * HD;
    const float* vg = g_v + (size_t)h * S_TOK * HD;

    // ---- prefetch tile 0 (K rows permuted) ----
    {
#pragma unroll
        for (int i = 0; i < 4; i++) {
            int idx = tid + i*128;
            int row = idx >> 4, ch = idx & 15;
            cp16(sb + K_OFF + (uint32_t)(kperm(row)*KSTR + ch*4)*4, kg + idx*4);
            cp16(sb + V_OFF + (uint32_t)(row*VSTR + ch*4)*4, vg + idx*4);
        }
        CP_COMMIT();
    }

    // ---- Q transform -> SMEM with dim permutation + scale*log2e folded ----
    {
        float y[64];
        transform_row_y(q + (size_t)s * (NH*HD) + (size_t)h * HD, y, g_PT[cam], px, py);
        const float SC = 0.18033688011112042f;  // (1/8)*log2(e)
        float4* dst = (float4*)&QP[(size_t)tid*QSTR];
#pragma unroll
        for (int i = 0; i < 16; i++) {
            int b = (i >> 1) * 8;
            if ((i & 1) == 0)
                dst[i] = make_float4(tf32r(y[b+0]*SC), tf32r(y[b+4]*SC),
                                     tf32r(y[b+1]*SC), tf32r(y[b+5]*SC));
            else
                dst[i] = make_float4(tf32r(y[b+2]*SC), tf32r(y[b+6]*SC),
                                     tf32r(y[b+3]*SC), tf32r(y[b+7]*SC));
        }
    }
    __syncthreads();

    float o[2][8][4];
#pragma unroll
    for (int m = 0; m < 2; m++)
#pragma unroll
        for (int nb = 0; nb < 8; nb++)
#pragma unroll
            for (int e = 0; e < 4; e++) o[m][nb][e] = 0.f;
    float mrow[4] = {-1e30f, -1e30f, -1e30f, -1e30f};
    float lsum[4] = {0.f, 0.f, 0.f, 0.f};

    const int r00 = w*32 + g;          // Q fragment rows
    const int qcol = 2*j;              // permuted: logical (j, j+4) -> (2j, 2j+1)

#pragma unroll 1
    for (int t = 0; t < NTILES; t++) {
        CP_WAIT0();
        __syncthreads();

        const float* Kf = smf + (K_OFF/4) + (t & 1) * (32*KSTR);
        const float* Vf = smf + (V_OFF/4) + (t & 1) * (32*VSTR);

        // ---- prefetch next tile ----
        if (t + 1 < NTILES) {
            const float* ksrc = kg + (size_t)(t+1) * KTILE * HD;
            const float* vsrc = vg + (size_t)(t+1) * KTILE * HD;
            uint32_t kb = sb + K_OFF + (uint32_t)((t+1) & 1) * K_BUF_B;
            uint32_t vb = sb + V_OFF + (uint32_t)((t+1) & 1) * V_BUF_B;
#pragma unroll
            for (int i = 0; i < 4; i++) {
                int idx = tid + i*128;
                int row = idx >> 4, ch = idx & 15;
                cp16(kb + (uint32_t)(kperm(row)*KSTR + ch*4)*4, ksrc + idx*4);
                cp16(vb + (uint32_t)(row*VSTR + ch*4)*4, vsrc + idx*4);
            }
            CP_COMMIT();
        }

        // ---- GEMM1: S = Q @ K^T; Q A-frags reloaded (LDS.64, dims permuted) ----
        float sc[2][4][4];
#pragma unroll
        for (int m = 0; m < 2; m++)
#pragma unroll
            for (int nb = 0; nb < 4; nb++)
#pragma unroll
                for (int e = 0; e < 4; e++) sc[m][nb][e] = 0.f;
#pragma unroll
        for (int tt = 0; tt < 8; tt++) {
            float2 f00 = *(const float2*)&QP[(r00   )*QSTR + tt*8 + qcol];
            float2 f01 = *(const float2*)&QP[(r00+ 8)*QSTR + tt*8 + qcol];
            float2 f10 = *(const float2*)&QP[(r00+16)*QSTR + tt*8 + qcol];
            float2 f11 = *(const float2*)&QP[(r00+24)*QSTR + tt*8 + qcol];
            uint32_t A0[4] = {__float_as_uint(f00.x), __float_as_uint(f01.x),
                              __float_as_uint(f00.y), __float_as_uint(f01.y)};
            uint32_t A1[4] = {__float_as_uint(f10.x), __float_as_uint(f11.x),
                              __float_as_uint(f10.y), __float_as_uint(f11.y)};
#pragma unroll
            for (int nb = 0; nb < 4; nb++) {
                float2 b = *(const float2*)&Kf[(nb*8 + g)*KSTR + tt*8 + qcol];
                mma_tf32(sc[0][nb], A0, b.x, b.y);
                mma_tf32(sc[1][nb], A1, b.x, b.y);
            }
        }

        // ---- online softmax (log2 domain) ----
        float rs[4];
#pragma unroll
        for (int m = 0; m < 2; m++)
#pragma unroll
            for (int hi = 0; hi < 2; hi++) {
                int rc = m*2 + hi;
                float mt = -1e30f;
#pragma unroll
                for (int nb = 0; nb < 4; nb++) {
                    mt = fmaxf(mt, sc[m][nb][hi*2]);
                    mt = fmaxf(mt, sc[m][nb][hi*2+1]);
                }
                mt = fmaxf(mt, __shfl_xor_sync(0xffffffffu, mt, 1));
                mt = fmaxf(mt, __shfl_xor_sync(0xffffffffu, mt, 2));
                float mn = fmaxf(mrow[rc], mt);
                rs[rc] = ex2(mrow[rc] - mn);
                mrow[rc] = mn;
                float ps = 0.f;
#pragma unroll
                for (int nb = 0; nb < 4; nb++) {
                    float p0 = ex2(sc[m][nb][hi*2]   - mn);
                    float p1 = ex2(sc[m][nb][hi*2+1] - mn);
                    sc[m][nb][hi*2] = p0; sc[m][nb][hi*2+1] = p1;
                    ps += p0 + p1;
                }
                ps += __shfl_xor_sync(0xffffffffu, ps, 1);
                ps += __shfl_xor_sync(0xffffffffu, ps, 2);
                lsum[rc] = lsum[rc]*rs[rc] + ps;
            }

        // ---- round P to tf32 in registers (GEMM2 A-fragment, key-permuted) ----
#pragma unroll
        for (int m = 0; m < 2; m++)
#pragma unroll
            for (int nb = 0; nb < 4; nb++)
#pragma unroll
                for (int e = 0; e < 4; e++) sc[m][nb][e] = tf32r(sc[m][nb][e]);

        // ---- rescale O (skipped when no row max moved) ----
        bool allone = (rs[0]==1.f) & (rs[1]==1.f) & (rs[2]==1.f) & (rs[3]==1.f);
        if (!__all_sync(0xffffffffu, allone)) {
#pragma unroll
            for (int m = 0; m < 2; m++)
#pragma unroll
                for (int nb = 0; nb < 8; nb++) {
                    o[m][nb][0] *= rs[m*2];   o[m][nb][1] *= rs[m*2];
                    o[m][nb][2] *= rs[m*2+1]; o[m][nb][3] *= rs[m*2+1];
                }
        }

        // ---- GEMM2: O += P @ V ----
#pragma unroll
        for (int tk = 0; tk < 4; tk++) {
            uint32_t pa0[4], pa1[4];
            pa0[0] = __float_as_uint(sc[0][tk][0]);
            pa0[1] = __float_as_uint(sc[0][tk][2]);
            pa0[2] = __float_as_uint(sc[0][tk][1]);
            pa0[3] = __float_as_uint(sc[0][tk][3]);
            pa1[0] = __float_as_uint(sc[1][tk][0]);
            pa1[1] = __float_as_uint(sc[1][tk][2]);
            pa1[2] = __float_as_uint(sc[1][tk][1]);
            pa1[3] = __float_as_uint(sc[1][tk][3]);
#pragma unroll
            for (int nb = 0; nb < 8; nb++) {
                const float* vr = Vf + (tk*8 + j)*VSTR + nb*8 + g;
                float b0 = vr[0], b1 = vr[4*VSTR];
                mma_tf32(o[0][nb], pa0, b0, b1);
                mma_tf32(o[1][nb], pa1, b0, b1);
            }
        }
    }

    // ---- normalize, exchange O through SMEM, epilogue ----
    __syncthreads();
    float inv[4];
#pragma unroll
    for (int rc = 0; rc < 4; rc++) inv[rc] = 1.0f / lsum[rc];
#pragma unroll
    for (int m = 0; m < 2; m++) {
        int r0 = w*32 + m*16 + g, r1 = r0 + 8;
#pragma unroll
        for (int nb = 0; nb < 8; nb++) {
            *(float2*)&QP[r0*QSTR + nb*8 + 2*j] =
                make_float2(o[m][nb][0]*inv[m*2],   o[m][nb][1]*inv[m*2]);
            *(float2*)&QP[r1*QSTR + nb*8 + 2*j] =
                make_float2(o[m][nb][2]*inv[m*2+1], o[m][nb][3]*inv[m*2+1]);
        }
    }
    __syncthreads();

    {
        float acc[64];
#pragma unroll
        for (int i = 0; i < 16; i++) {
            float4 tv = *(const float4*)&QP[(size_t)tid*QSTR + i*4];
            acc[4*i+0]=tv.x; acc[4*i+1]=tv.y; acc[4*i+2]=tv.z; acc[4*i+3]=tv.w;
        }
        float y[64];
        const float* M = g_P[cam];
#pragma unroll
        for (int gg = 0; gg < 8; gg++)
#pragma unroll
            for (int i = 0; i < 4; i++)
                y[gg*4+i] = M[i*4+0]*acc[gg*4+0] + M[i*4+1]*acc[gg*4+1]
                          + M[i*4+2]*acc[gg*4+2] + M[i*4+3]*acc[gg*4+3];
#pragma unroll
        for (int i = 0; i < 8; i++) {
            float c1 = g_cos[px][i], s1 = g_sin[px][i];
            y[32+i] = c1*acc[32+i] - s1*acc[40+i];
            y[40+i] = s1*acc[32+i] + c1*acc[40+i];
            float c2 = g_cos[py][i], s2 = g_sin[py][i];
            y[48+i] = c2*acc[48+i] - s2*acc[56+i];
            y[56+i] = s2*acc[48+i] + c2*acc[56+i];
        }
        float4* o4 = (float4*)(out + (size_t)s * (NH*HD) + (size_t)h * HD);
#pragma unroll
        for (int i = 0; i < 16; i++)
            o4[i] = make_float4(y[4*i+0], y[4*i+1], y[4*i+2], y[4*i+3]);
    }
}

// ---------------------------------------------------------------------------
extern "C" void kernel_launch(void* const* d_in, const int* in_sizes, int n_in,
                              void* d_out, int out_size) {
    const float* q  = (const float*)d_in[0];
    const float* k  = (const float*)d_in[1];
    const float* v  = (const float*)d_in[2];
    const float* vm = (const float*)d_in[3];
    const float* Ks = (const float*)d_in[4];
    float* out = (float*)d_out;

    cudaFuncSetAttribute(attn_kernel, cudaFuncAttributeMaxDynamicSharedMemorySize, SMEM_BYTES);

    prep_kernel<<<1, 32>>>(vm, Ks);
    transform_kv_kernel<<<(NROWS + 255) / 256, 256>>>(k, v);
    attn_kernel<<<dim3(S_TOK / QTILE, NH), QTILE, SMEM_BYTES>>>(q, out);
}

// round 9
// speedup vs baseline: 1.2369x; 1.2369x over previous
#include <cuda_runtime.h>
#include <math.h>
#include <cstdint>

#define S_TOK 4096
#define NH    12
#define HD    64
#define NROWS (S_TOK*NH)
#define QTILE 128
#define KTILE 32
#define NTILES (S_TOK/KTILE)

// SMEM geometry (floats / bytes); triple-buffered K and V
#define KSTR 68
#define VSTR 72
#define QSTR 76
#define K_OFF   0
#define K_BUF_B (32*KSTR*4)              // 8704
#define V_OFF   (3*K_BUF_B)              // 26112
#define V_BUF_B (32*VSTR*4)              // 9216
#define QP_OFF  (V_OFF + 3*V_BUF_B)      // 53760
#define SMEM_BYTES (QP_OFF + 128*QSTR*4) // 92672 -> 2 CTAs/SM

// ---------------- scratch ---------------------------------------------------
__device__ float g_k[(size_t)NH*S_TOK*HD];   // [h][s][d'] dims permuted in 8-groups
__device__ float g_v[(size_t)NH*S_TOK*HD];   // [h][s][d]  natural
__device__ float g_P[4][16];
__device__ float g_PT[4][16];
__device__ float g_Pinv[4][16];
__device__ float g_cos[32][8];
__device__ float g_sin[32][8];

__device__ __forceinline__ float tf32r(float x) {
    float r; asm("cvt.rna.tf32.f32 %0,%1;" : "=f"(r) : "f"(x)); return r;
}
__device__ __forceinline__ float ex2(float x) {
    float y; asm("ex2.approx.ftz.f32 %0,%1;" : "=f"(y) : "f"(x)); return y;
}
__device__ __forceinline__ uint32_t smem_u32(const void* p) {
    uint32_t a;
    asm("{ .reg .u64 t; cvta.to.shared.u64 t, %1; cvt.u32.u64 %0, t; }" : "=r"(a) : "l"(p));
    return a;
}
__device__ __forceinline__ void cp16(uint32_t dst, const void* src) {
    asm volatile("cp.async.cg.shared.global [%0], [%1], 16;" :: "r"(dst), "l"(src) : "memory");
}
#define CP_COMMIT() asm volatile("cp.async.commit_group;" ::: "memory")
#define CP_WAIT0()  asm volatile("cp.async.wait_group 0;" ::: "memory")
#define CP_WAIT1()  asm volatile("cp.async.wait_group 1;" ::: "memory")

__device__ __forceinline__ void mma_tf32(float* d, const uint32_t* a, float b0f, float b1f) {
    uint32_t b0 = __float_as_uint(b0f), b1 = __float_as_uint(b1f);
    asm volatile("mma.sync.aligned.m16n8k8.row.col.f32.tf32.tf32.f32 "
        "{%0,%1,%2,%3}, {%4,%5,%6,%7}, {%8,%9}, {%0,%1,%2,%3};"
        : "+f"(d[0]), "+f"(d[1]), "+f"(d[2]), "+f"(d[3])
        : "r"(a[0]), "r"(a[1]), "r"(a[2]), "r"(a[3]), "r"(b0), "r"(b1));
}

__device__ __forceinline__ void mm4(const float* A, const float* B, float* Cm) {
#pragma unroll
    for (int i = 0; i < 4; i++)
#pragma unroll
        for (int j = 0; j < 4; j++) {
            float s = 0.f;
#pragma unroll
            for (int kk = 0; kk < 4; kk++) s += A[i*4+kk] * B[kk*4+j];
            Cm[i*4+j] = s;
        }
}

// key permutation within 8-group (GEMM1 D-layout == GEMM2 A-layout)
__device__ __forceinline__ int kperm(int row) {
    int b = row & 7;
    int pb = (b < 4) ? (b << 1) : (((b - 4) << 1) | 1);
    return (row & ~7) | pb;
}

// ---------------------------------------------------------------------------
__global__ void prep_kernel(const float* __restrict__ vm, const float* __restrict__ Ks) {
    int t = threadIdx.x;
    if (t < 32) {
        float L = log2f(100.0f);
#pragma unroll
        for (int i = 0; i < 8; i++) {
            float f = exp2f(-L * (float)i / 8.0f);
            float sv, cv; sincosf((float)t * f, &sv, &cv);
            g_cos[t][i] = cv; g_sin[t][i] = sv;
        }
    }
    if (t < 4) {
        int c = t;
        const float* V  = vm + c*16;
        const float* Kc = Ks + c*9;
        float a = Kc[0] * (1.0f/512.0f);
        float b = Kc[4] * (1.0f/512.0f);
        float u = Kc[2] * (1.0f/512.0f) - 0.5f;
        float w = Kc[5] * (1.0f/512.0f) - 0.5f;
        float K4[16] = {a,0,u,0, 0,b,w,0, 0,0,1,0, 0,0,0,1};
        float Vl[16];
#pragma unroll
        for (int i = 0; i < 16; i++) Vl[i] = V[i];
        float P[16];
        mm4(K4, Vl, P);
#pragma unroll
        for (int i = 0; i < 4; i++)
#pragma unroll
            for (int jj = 0; jj < 4; jj++) { g_P[c][i*4+jj] = P[i*4+jj]; g_PT[c][i*4+jj] = P[jj*4+i]; }
        float Sm[16];
#pragma unroll
        for (int i = 0; i < 3; i++)
#pragma unroll
            for (int jj = 0; jj < 3; jj++) Sm[i*4+jj] = Vl[jj*4+i];
#pragma unroll
        for (int i = 0; i < 3; i++)
            Sm[i*4+3] = -(Sm[i*4+0]*Vl[3] + Sm[i*4+1]*Vl[7] + Sm[i*4+2]*Vl[11]);
        Sm[12]=0.f; Sm[13]=0.f; Sm[14]=0.f; Sm[15]=1.f;
        float Ki[16] = {1.0f/a,0,-u/a,0, 0,1.0f/b,-w/b,0, 0,0,1,0, 0,0,0,1};
        float Pi[16];
        mm4(Sm, Ki, Pi);
#pragma unroll
        for (int i = 0; i < 16; i++) g_Pinv[c][i] = Pi[i];
    }
}

// ---------------------------------------------------------------------------
__device__ __forceinline__ void transform_row_y(
    const float* __restrict__ in, float* __restrict__ y,
    const float* M, int px, int py)
{
    float x[64];
    const float4* in4 = (const float4*)in;
#pragma unroll
    for (int i = 0; i < 16; i++) {
        float4 tv = in4[i];
        x[4*i+0]=tv.x; x[4*i+1]=tv.y; x[4*i+2]=tv.z; x[4*i+3]=tv.w;
    }
#pragma unroll
    for (int g = 0; g < 8; g++)
#pragma unroll
        for (int i = 0; i < 4; i++)
            y[g*4+i] = M[i*4+0]*x[g*4+0] + M[i*4+1]*x[g*4+1]
                     + M[i*4+2]*x[g*4+2] + M[i*4+3]*x[g*4+3];
#pragma unroll
    for (int i = 0; i < 8; i++) {
        float c1 = g_cos[px][i], s1 = g_sin[px][i];
        y[32+i] =  c1*x[32+i] + s1*x[40+i];
        y[40+i] = -s1*x[32+i] + c1*x[40+i];
        float c2 = g_cos[py][i], s2 = g_sin[py][i];
        y[48+i] =  c2*x[48+i] + s2*x[56+i];
        y[56+i] = -s2*x[48+i] + c2*x[56+i];
    }
}

__global__ void transform_kv_kernel(const float* __restrict__ k, const float* __restrict__ v) {
    int r = blockIdx.x * blockDim.x + threadIdx.x;
    if (r >= NROWS) return;
    int s = r / NH;
    int h = r - s * NH;
    int c  = s >> 10;
    int px = s & 31;
    int py = (s >> 5) & 31;
    float M[16];
#pragma unroll
    for (int i = 0; i < 16; i++) M[i] = g_Pinv[c][i];
    size_t ibase = (size_t)r * HD;
    size_t obase = ((size_t)h * S_TOK + s) * HD;

    float y[64];
    // K: dim-permuted within 8-groups (register shuffle before coalesced stores)
    transform_row_y(k + ibase, y, M, px, py);
    {
        float4* o4 = (float4*)(g_k + obase);
#pragma unroll
        for (int i = 0; i < 16; i++) {
            int b = (i >> 1) * 8;
            if ((i & 1) == 0)
                o4[i] = make_float4(tf32r(y[b+0]), tf32r(y[b+4]), tf32r(y[b+1]), tf32r(y[b+5]));
            else
                o4[i] = make_float4(tf32r(y[b+2]), tf32r(y[b+6]), tf32r(y[b+3]), tf32r(y[b+7]));
        }
    }
    // V: natural order
    transform_row_y(v + ibase, y, M, px, py);
    {
        float4* o4 = (float4*)(g_v + obase);
#pragma unroll
        for (int i = 0; i < 16; i++)
            o4[i] = make_float4(tf32r(y[4*i+0]), tf32r(y[4*i+1]), tf32r(y[4*i+2]), tf32r(y[4*i+3]));
    }
}

// ---------------------------------------------------------------------------
// Pipelined flash attention: iteration t runs rescale; GEMM2(t) || GEMM1(t+1);
// softmax(t+1). Triple-buffered K/V (cp.async), key-permuted K, dim-permuted
// Q/K (LDS.64 frags), persistent Q fragments.
// ---------------------------------------------------------------------------

#define STAGE(BUF, T) do { \
    const float* ksrc_ = kg + (size_t)(T) * KTILE * HD; \
    const float* vsrc_ = vg + (size_t)(T) * KTILE * HD; \
    uint32_t kb_ = sb + K_OFF + (uint32_t)(BUF) * K_BUF_B; \
    uint32_t vb_ = sb + V_OFF + (uint32_t)(BUF) * V_BUF_B; \
    _Pragma("unroll") \
    for (int i_ = 0; i_ < 4; i_++) { \
        int idx_ = tid + i_*128; \
        int row_ = idx_ >> 4, ch_ = idx_ & 15; \
        cp16(kb_ + (uint32_t)(kperm(row_)*KSTR + ch_*4)*4, ksrc_ + idx_*4); \
        cp16(vb_ + (uint32_t)(row_*VSTR + ch_*4)*4, vsrc_ + idx_*4); \
    } \
    CP_COMMIT(); \
} while(0)

#define SOFTMAX(SCN) do { \
    _Pragma("unroll") \
    for (int m_ = 0; m_ < 2; m_++) \
    _Pragma("unroll") \
    for (int hi_ = 0; hi_ < 2; hi_++) { \
        int rc_ = m_*2 + hi_; \
        float mt_ = -1e30f; \
        _Pragma("unroll") \
        for (int nb_ = 0; nb_ < 4; nb_++) { \
            mt_ = fmaxf(mt_, SCN[m_][nb_][hi_*2]); \
            mt_ = fmaxf(mt_, SCN[m_][nb_][hi_*2+1]); \
        } \
        mt_ = fmaxf(mt_, __shfl_xor_sync(0xffffffffu, mt_, 1)); \
        mt_ = fmaxf(mt_, __shfl_xor_sync(0xffffffffu, mt_, 2)); \
        float mn_ = fmaxf(mrow[rc_], mt_); \
        rs[rc_] = ex2(mrow[rc_] - mn_); \
        mrow[rc_] = mn_; \
        float ps_ = 0.f; \
        _Pragma("unroll") \
        for (int nb_ = 0; nb_ < 4; nb_++) { \
            float p0_ = ex2(SCN[m_][nb_][hi_*2]   - mn_); \
            float p1_ = ex2(SCN[m_][nb_][hi_*2+1] - mn_); \
            ps_ += p0_ + p1_; \
            SCN[m_][nb_][hi_*2]   = tf32r(p0_); \
            SCN[m_][nb_][hi_*2+1] = tf32r(p1_); \
        } \
        ps_ += __shfl_xor_sync(0xffffffffu, ps_, 1); \
        ps_ += __shfl_xor_sync(0xffffffffu, ps_, 2); \
        lsum[rc_] = lsum[rc_]*rs[rc_] + ps_; \
    } \
} while(0)

#define RESCALE() do { \
    bool a1_ = (rs[0]==1.f) & (rs[1]==1.f) & (rs[2]==1.f) & (rs[3]==1.f); \
    if (!__all_sync(0xffffffffu, a1_)) { \
        _Pragma("unroll") \
        for (int m_ = 0; m_ < 2; m_++) \
        _Pragma("unroll") \
        for (int nb_ = 0; nb_ < 8; nb_++) { \
            o[m_][nb_][0] *= rs[m_*2];   o[m_][nb_][1] *= rs[m_*2]; \
            o[m_][nb_][2] *= rs[m_*2+1]; o[m_][nb_][3] *= rs[m_*2+1]; \
        } \
    } \
} while(0)

// GEMM2(t) using SCP + V buf, fused with GEMM1(t+1) into SCN from K buf
#define TILE_BODY(T, SCP, SCN) do { \
    CP_WAIT0(); __syncthreads(); \
    if ((T)+2 < NTILES) STAGE(bf, (T)+2); \
    const float* Kf_ = smf + (K_OFF/4) + bn*(K_BUF_B/4); \
    const float* Vf_ = smf + (V_OFF/4) + bc*(V_BUF_B/4); \
    _Pragma("unroll") \
    for (int m_ = 0; m_ < 2; m_++) \
    _Pragma("unroll") \
    for (int nb_ = 0; nb_ < 4; nb_++) \
    _Pragma("unroll") \
    for (int e_ = 0; e_ < 4; e_++) SCN[m_][nb_][e_] = 0.f; \
    RESCALE(); \
    _Pragma("unroll") \
    for (int st_ = 0; st_ < 4; st_++) { \
        _Pragma("unroll") \
        for (int u_ = 0; u_ < 2; u_++) { \
            int tt_ = 2*st_ + u_; \
            _Pragma("unroll") \
            for (int nb_ = 0; nb_ < 4; nb_++) { \
                float2 b_ = *(const float2*)&Kf_[(nb_*8 + g)*KSTR + tt_*8 + qcol]; \
                mma_tf32(SCN[0][nb_], qa[0][tt_], b_.x, b_.y); \
                mma_tf32(SCN[1][nb_], qa[1][tt_], b_.x, b_.y); \
            } \
        } \
        uint32_t pa0_[4] = {__float_as_uint(SCP[0][st_][0]), __float_as_uint(SCP[0][st_][2]), \
                            __float_as_uint(SCP[0][st_][1]), __float_as_uint(SCP[0][st_][3])}; \
        uint32_t pa1_[4] = {__float_as_uint(SCP[1][st_][0]), __float_as_uint(SCP[1][st_][2]), \
                            __float_as_uint(SCP[1][st_][1]), __float_as_uint(SCP[1][st_][3])}; \
        _Pragma("unroll") \
        for (int nb_ = 0; nb_ < 8; nb_++) { \
            const float* vr_ = Vf_ + (st_*8 + j)*VSTR + nb_*8 + g; \
            mma_tf32(o[0][nb_], pa0_, vr_[0], vr_[4*VSTR]); \
            mma_tf32(o[1][nb_], pa1_, vr_[0], vr_[4*VSTR]); \
        } \
    } \
    SOFTMAX(SCN); \
    { int tb_ = bc; bc = bn; bn = bf; bf = tb_; } \
} while(0)

__global__ void __launch_bounds__(QTILE)
attn_kernel(const float* __restrict__ q, float* __restrict__ out) {
    extern __shared__ char smraw[];
    const uint32_t sb = smem_u32(smraw);
    float* smf = (float*)smraw;
    float* QP  = (float*)(smraw + QP_OFF);

    const int tid  = threadIdx.x;
    const int w    = tid >> 5, lane = tid & 31;
    const int g    = lane >> 2, j = lane & 3;
    const int h    = blockIdx.y;
    const int s    = blockIdx.x * QTILE + tid;
    const int cam  = s >> 10, px = s & 31, py = (s >> 5) & 31;
    const int qcol = 2*j;

    const float* kg = g_k + (size_t)h * S_TOK * HD;
    const float* vg = g_v + (size_t)h * S_TOK * HD;

    STAGE(0, 0);
    STAGE(1, 1);

    // ---- Q transform -> SMEM (dim-permuted, scale*log2e folded) ----
    {
        float y[64];
        transform_row_y(q + (size_t)s * (NH*HD) + (size_t)h * HD, y, g_PT[cam], px, py);
        const float SC = 0.18033688011112042f;  // (1/8)*log2(e)
        float4* dst = (float4*)&QP[(size_t)tid*QSTR];
#pragma unroll
        for (int i = 0; i < 16; i++) {
            int b = (i >> 1) * 8;
            if ((i & 1) == 0)
                dst[i] = make_float4(tf32r(y[b+0]*SC), tf32r(y[b+4]*SC),
                                     tf32r(y[b+1]*SC), tf32r(y[b+5]*SC));
            else
                dst[i] = make_float4(tf32r(y[b+2]*SC), tf32r(y[b+6]*SC),
                                     tf32r(y[b+3]*SC), tf32r(y[b+7]*SC));
        }
    }
    CP_WAIT1();
    __syncthreads();   // QP visible to all; K/V tile0 visible

    // ---- persistent Q A-fragments (LDS.64, permuted cols) ----
    uint32_t qa[2][8][4];
    {
        const int r00 = w*32 + g;
#pragma unroll
        for (int tt = 0; tt < 8; tt++) {
            float2 f00 = *(const float2*)&QP[(r00   )*QSTR + tt*8 + qcol];
            float2 f01 = *(const float2*)&QP[(r00+ 8)*QSTR + tt*8 + qcol];
            float2 f10 = *(const float2*)&QP[(r00+16)*QSTR + tt*8 + qcol];
            float2 f11 = *(const float2*)&QP[(r00+24)*QSTR + tt*8 + qcol];
            qa[0][tt][0] = __float_as_uint(f00.x); qa[0][tt][1] = __float_as_uint(f01.x);
            qa[0][tt][2] = __float_as_uint(f00.y); qa[0][tt][3] = __float_as_uint(f01.y);
            qa[1][tt][0] = __float_as_uint(f10.x); qa[1][tt][1] = __float_as_uint(f11.x);
            qa[1][tt][2] = __float_as_uint(f10.y); qa[1][tt][3] = __float_as_uint(f11.y);
        }
    }

    float o[2][8][4];
#pragma unroll
    for (int m = 0; m < 2; m++)
#pragma unroll
        for (int nb = 0; nb < 8; nb++)
#pragma unroll
            for (int e = 0; e < 4; e++) o[m][nb][e] = 0.f;
    float mrow[4] = {-1e30f, -1e30f, -1e30f, -1e30f};
    float lsum[4] = {0.f, 0.f, 0.f, 0.f};
    float rs[4];
    float scA[2][4][4], scB[2][4][4];
    int bc = 0, bn = 1, bf = 2;

    // ---- preamble: GEMM1(0) + softmax(0) into scA ----
    {
        const float* Kf_ = smf + (K_OFF/4);
#pragma unroll
        for (int m = 0; m < 2; m++)
#pragma unroll
            for (int nb = 0; nb < 4; nb++)
#pragma unroll
                for (int e = 0; e < 4; e++) scA[m][nb][e] = 0.f;
#pragma unroll
        for (int tt = 0; tt < 8; tt++)
#pragma unroll
            for (int nb = 0; nb < 4; nb++) {
                float2 b = *(const float2*)&Kf_[(nb*8 + g)*KSTR + tt*8 + qcol];
                mma_tf32(scA[0][nb], qa[0][tt], b.x, b.y);
                mma_tf32(scA[1][nb], qa[1][tt], b.x, b.y);
            }
        SOFTMAX(scA);
    }

    // ---- pipelined main loop: body(t) = rescale; GEMM2(t) || GEMM1(t+1); softmax(t+1)
#pragma unroll 1
    for (int t = 0; t < NTILES-2; t += 2) {
        TILE_BODY(t,   scA, scB);
        TILE_BODY(t+1, scB, scA);
    }
    TILE_BODY(NTILES-2, scA, scB);   // t=126: GEMM2(126), GEMM1(127)->scB, softmax(127)

    // ---- final tile: rescale + GEMM2(127) ----
    {
        const float* Vf_ = smf + (V_OFF/4) + bc*(V_BUF_B/4);
        RESCALE();
#pragma unroll
        for (int st = 0; st < 4; st++) {
            uint32_t pa0[4] = {__float_as_uint(scB[0][st][0]), __float_as_uint(scB[0][st][2]),
                               __float_as_uint(scB[0][st][1]), __float_as_uint(scB[0][st][3])};
            uint32_t pa1[4] = {__float_as_uint(scB[1][st][0]), __float_as_uint(scB[1][st][2]),
                               __float_as_uint(scB[1][st][1]), __float_as_uint(scB[1][st][3])};
#pragma unroll
            for (int nb = 0; nb < 8; nb++) {
                const float* vr = Vf_ + (st*8 + j)*VSTR + nb*8 + g;
                mma_tf32(o[0][nb], pa0, vr[0], vr[4*VSTR]);
                mma_tf32(o[1][nb], pa1, vr[0], vr[4*VSTR]);
            }
        }
    }

    // ---- normalize, exchange O through SMEM, epilogue ----
    __syncthreads();
    float inv[4];
#pragma unroll
    for (int rc = 0; rc < 4; rc++) inv[rc] = 1.0f / lsum[rc];
#pragma unroll
    for (int m = 0; m < 2; m++) {
        int r0 = w*32 + m*16 + g, r1 = r0 + 8;
#pragma unroll
        for (int nb = 0; nb < 8; nb++) {
            *(float2*)&QP[r0*QSTR + nb*8 + 2*j] =
                make_float2(o[m][nb][0]*inv[m*2],   o[m][nb][1]*inv[m*2]);
            *(float2*)&QP[r1*QSTR + nb*8 + 2*j] =
                make_float2(o[m][nb][2]*inv[m*2+1], o[m][nb][3]*inv[m*2+1]);
        }
    }
    __syncthreads();

    {
        float acc[64];
#pragma unroll
        for (int i = 0; i < 16; i++) {
            float4 tv = *(const float4*)&QP[(size_t)tid*QSTR + i*4];
            acc[4*i+0]=tv.x; acc[4*i+1]=tv.y; acc[4*i+2]=tv.z; acc[4*i+3]=tv.w;
        }
        float y[64];
        const float* M = g_P[cam];
#pragma unroll
        for (int gg = 0; gg < 8; gg++)
#pragma unroll
            for (int i = 0; i < 4; i++)
                y[gg*4+i] = M[i*4+0]*acc[gg*4+0] + M[i*4+1]*acc[gg*4+1]
                          + M[i*4+2]*acc[gg*4+2] + M[i*4+3]*acc[gg*4+3];
#pragma unroll
        for (int i = 0; i < 8; i++) {
            float c1 = g_cos[px][i], s1 = g_sin[px][i];
            y[32+i] = c1*acc[32+i] - s1*acc[40+i];
            y[40+i] = s1*acc[32+i] + c1*acc[40+i];
            float c2 = g_cos[py][i], s2 = g_sin[py][i];
            y[48+i] = c2*acc[48+i] - s2*acc[56+i];
            y[56+i] = s2*acc[48+i] + c2*acc[56+i];
        }
        float4* o4 = (float4*)(out + (size_t)s * (NH*HD) + (size_t)h * HD);
#pragma unroll
        for (int i = 0; i < 16; i++)
            o4[i] = make_float4(y[4*i+0], y[4*i+1], y[4*i+2], y[4*i+3]);
    }
}

// ---------------------------------------------------------------------------
extern "C" void kernel_launch(void* const* d_in, const int* in_sizes, int n_in,
                              void* d_out, int out_size) {
    const float* q  = (const float*)d_in[0];
    const float* k  = (const float*)d_in[1];
    const float* v  = (const float*)d_in[2];
    const float* vm = (const float*)d_in[3];
    const float* Ks = (const float*)d_in[4];
    float* out = (float*)d_out;

    cudaFuncSetAttribute(attn_kernel, cudaFuncAttributeMaxDynamicSharedMemorySize, SMEM_BYTES);

    prep_kernel<<<1, 32>>>(vm, Ks);
    transform_kv_kernel<<<(NROWS + 255) / 256, 256>>>(k, v);
    attn_kernel<<<dim3(S_TOK / QTILE, NH), QTILE, SMEM_BYTES>>>(q, out);
}